// round 5
// baseline (speedup 1.0000x reference)
#include <cuda_runtime.h>
#include <cuda_fp16.h>
#include <cstdint>

#define NN 50000
#define DIN 256
#define NC 8
#define NE 1600000

// ---- static device scratch (allocation-free contract) ----
__device__ __align__(16) float g_logb0[NN * NC];
__device__ __align__(16) float g_B[NN * NC];
__device__ __align__(16) float g_agg[NN * NC];
__device__ __align__(16) float g_m0[NN * NC];     // step-0 per-node message
__device__ __align__(16) __half g_Rn[NN * NC];    // step-0 per-node reciprocal msg
__device__ __align__(16) __half g_RA[NE * NC];    // fp16 reciprocal messages (ping)
__device__ __align__(16) __half g_RB[NE * NC];    // fp16 reciprocal messages (pong)
__device__ int g_src[NE];
__device__ int g_dst[NE];
__device__ int g_rv[NE];
__device__ int g_srv[NE];                          // src[rv[e]]
__device__ int g_odd_nonzero;  // !=0 -> indices are int32; ==0 -> int64

__device__ __forceinline__ float frcp(float x) {
    float r;
    asm("rcp.approx.f32 %0, %1;" : "=f"(r) : "f"(x));
    return r;
}

#define CP_ASYNC_16(saddr, gptr) \
    asm volatile("cp.async.cg.shared.global [%0], [%1], 16;" :: "r"(saddr), "l"(gptr))
#define CP_COMMIT() asm volatile("cp.async.commit_group;")
#define CP_WAIT(n) asm volatile("cp.async.wait_group %0;" :: "n"(n))

// --- dtype detection ---
__global__ void reset_flag_kernel() { g_odd_nonzero = 0; }

// Sample odd 32-bit words of the first 4096 index pairs.
// int64 layout: high halves of nonneg values < 2^31 -> all zero.
// int32 layout: uniform node ids -> P(all zero) ~ 0.
__global__ void __launch_bounds__(256) detect_kernel(const int* __restrict__ w) {
    int v = 0;
#pragma unroll
    for (int j = 0; j < 16; j++) {
        int i = threadIdx.x + j * 256;
        v |= w[2 * i + 1];
    }
    unsigned any = __ballot_sync(0xffffffffu, v != 0);
    if ((threadIdx.x & 31) == 0 && any) atomicOr(&g_odd_nonzero, 1);
}

// index compaction (int64 or int32 source, selected by runtime flag)
__global__ void __launch_bounds__(256) prep_kernel(const void* __restrict__ ei,
                                                   const void* __restrict__ rv) {
    int e = blockIdx.x * 256 + threadIdx.x;
    if (e >= NE) return;
    if (g_odd_nonzero) {  // int32 inputs
        const int* ei32 = (const int*)ei;
        const int* rv32 = (const int*)rv;
        g_src[e] = ei32[e];
        g_dst[e] = ei32[NE + e];
        g_rv[e] = rv32[e];
    } else {  // int64 inputs
        const long long* ei64 = (const long long*)ei;
        const long long* rv64 = (const long long*)rv;
        g_src[e] = (int)ei64[e];
        g_dst[e] = (int)ei64[NE + e];
        g_rv[e] = (int)rv64[e];
    }
}

// srv[e] = src[rv[e]]  (lets step 1 gather from the 800KB node table)
__global__ void __launch_bounds__(256) prep2_kernel() {
    int e = blockIdx.x * 256 + threadIdx.x;
    if (e < NE) g_srv[e] = g_src[g_rv[e]];
}

// log_b0 = log_softmax(x @ W + b); B = exp(log_b0); agg = log_b0;
// m0 = log(1+beta*B) - C2; Rn = 1/(1+beta*B).
// One thread per node; x streamed through double-buffered cp.async tiles.
#define TTB 64
__global__ void __launch_bounds__(TTB) transform_kernel(const float* __restrict__ x,
                                                        const float* __restrict__ W,
                                                        const float* __restrict__ bias) {
    __shared__ __align__(16) float sx[2][TTB][36];   // pitch 36 floats (144B)
    __shared__ __align__(16) float sW[DIN * NC];
    __shared__ float sb[NC];

    int tid = threadIdx.x;
    for (int i = tid; i < DIN * NC; i += TTB) sW[i] = W[i];
    if (tid < NC) sb[tid] = bias[tid];

    int node0 = blockIdx.x * TTB;
    int n = node0 + tid;

    unsigned int sx_base = (unsigned int)__cvta_generic_to_shared(&sx[0][0][0]);

    // issue chunk 0 into buffer 0
#pragma unroll
    for (int i = 0; i < 8; i++) {
        int lin = i * TTB + tid;
        int row = lin >> 3, c4 = lin & 7;
        int nr = node0 + row;
        if (nr < NN) {
            unsigned int sa = sx_base + (unsigned int)((row * 36 + c4 * 4) * 4);
            CP_ASYNC_16(sa, x + (size_t)nr * DIN + c4 * 4);
        }
    }
    CP_COMMIT();

    float acc[NC] = {0.f, 0.f, 0.f, 0.f, 0.f, 0.f, 0.f, 0.f};
    int buf = 0;

#pragma unroll 1
    for (int chunk = 0; chunk < DIN / 32; chunk++) {
        if (chunk + 1 < DIN / 32) {
            int ob = buf ^ 1;
#pragma unroll
            for (int i = 0; i < 8; i++) {
                int lin = i * TTB + tid;
                int row = lin >> 3, c4 = lin & 7;
                int nr = node0 + row;
                if (nr < NN) {
                    unsigned int sa = sx_base +
                                      (unsigned int)(((ob * TTB + row) * 36 + c4 * 4) * 4);
                    CP_ASYNC_16(sa, x + (size_t)nr * DIN + (chunk + 1) * 32 + c4 * 4);
                }
            }
            CP_COMMIT();
            CP_WAIT(1);
        } else {
            CP_WAIT(0);
        }
        __syncthreads();

#pragma unroll
        for (int k4 = 0; k4 < 8; k4++) {
            float4 xv = *(const float4*)&sx[buf][tid][k4 * 4];
            int kg = chunk * 32 + k4 * 4;
            float xs[4] = {xv.x, xv.y, xv.z, xv.w};
#pragma unroll
            for (int j = 0; j < 4; j++) {
                float4 w0 = *(const float4*)&sW[(kg + j) * NC];
                float4 w1 = *(const float4*)&sW[(kg + j) * NC + 4];
                acc[0] = fmaf(xs[j], w0.x, acc[0]);
                acc[1] = fmaf(xs[j], w0.y, acc[1]);
                acc[2] = fmaf(xs[j], w0.z, acc[2]);
                acc[3] = fmaf(xs[j], w0.w, acc[3]);
                acc[4] = fmaf(xs[j], w1.x, acc[4]);
                acc[5] = fmaf(xs[j], w1.y, acc[5]);
                acc[6] = fmaf(xs[j], w1.z, acc[6]);
                acc[7] = fmaf(xs[j], w1.w, acc[7]);
            }
        }
        __syncthreads();
        buf ^= 1;
    }

    if (n >= NN) return;

    float m = -3.4e38f;
#pragma unroll
    for (int c = 0; c < NC; c++) {
        acc[c] += sb[c];
        m = fmaxf(m, acc[c]);
    }
    float e[NC], S = 0.f;
#pragma unroll
    for (int c = 0; c < NC; c++) {
        e[c] = __expf(acc[c] - m);
        S += e[c];
    }
    float lS = __logf(S);
    float iS = frcp(S);

    const float beta = 19.085536923187668f;  // e^3 - 1
    const float C2 = 3.2990000f;             // log(e^3 + 7)

    float lb[NC], B[NC], m0[NC], Rn[NC];
#pragma unroll
    for (int c = 0; c < NC; c++) {
        lb[c] = acc[c] - m - lS;
        B[c] = e[c] * iS;
        float qp = fmaf(beta, B[c], 1.0f);
        m0[c] = __logf(qp) - C2;
        Rn[c] = frcp(qp);
    }

    *(float4*)(g_logb0 + n * NC) = make_float4(lb[0], lb[1], lb[2], lb[3]);
    *(float4*)(g_logb0 + n * NC + 4) = make_float4(lb[4], lb[5], lb[6], lb[7]);
    *(float4*)(g_agg + n * NC) = make_float4(lb[0], lb[1], lb[2], lb[3]);
    *(float4*)(g_agg + n * NC + 4) = make_float4(lb[4], lb[5], lb[6], lb[7]);
    *(float4*)(g_B + n * NC) = make_float4(B[0], B[1], B[2], B[3]);
    *(float4*)(g_B + n * NC + 4) = make_float4(B[4], B[5], B[6], B[7]);
    *(float4*)(g_m0 + n * NC) = make_float4(m0[0], m0[1], m0[2], m0[3]);
    *(float4*)(g_m0 + n * NC + 4) = make_float4(m0[4], m0[5], m0[6], m0[7]);
    uint4 rq;
    __half2* rh = (__half2*)&rq;
    rh[0] = __floats2half2_rn(Rn[0], Rn[1]);
    rh[1] = __floats2half2_rn(Rn[2], Rn[3]);
    rh[2] = __floats2half2_rn(Rn[4], Rn[5]);
    rh[3] = __floats2half2_rn(Rn[6], Rn[7]);
    *(uint4*)(g_Rn + n * NC) = rq;
}

// step 0: agg[dst] += m0[src]  (pure gather-scatter, 2 edges/thread)
__global__ void __launch_bounds__(256) step0_kernel() {
    int t = blockIdx.x * 256 + threadIdx.x;
    int e0 = t * 2;
    int2 ss = *(const int2*)(g_src + e0);
    int2 dd = *(const int2*)(g_dst + e0);

    float4 a0 = *(const float4*)(g_m0 + ss.x * NC);
    float4 a1 = *(const float4*)(g_m0 + ss.x * NC + 4);
    float4 b0 = *(const float4*)(g_m0 + ss.y * NC);
    float4 b1 = *(const float4*)(g_m0 + ss.y * NC + 4);

    float* p0 = g_agg + dd.x * NC;
    float* p1 = g_agg + dd.y * NC;
    asm volatile("red.global.add.v4.f32 [%0], {%1,%2,%3,%4};"
                 :: "l"(p0), "f"(a0.x), "f"(a0.y), "f"(a0.z), "f"(a0.w) : "memory");
    asm volatile("red.global.add.v4.f32 [%0], {%1,%2,%3,%4};"
                 :: "l"(p0 + 4), "f"(a1.x), "f"(a1.y), "f"(a1.z), "f"(a1.w) : "memory");
    asm volatile("red.global.add.v4.f32 [%0], {%1,%2,%3,%4};"
                 :: "l"(p1), "f"(b0.x), "f"(b0.y), "f"(b0.z), "f"(b0.w) : "memory");
    asm volatile("red.global.add.v4.f32 [%0], {%1,%2,%3,%4};"
                 :: "l"(p1 + 4), "f"(b1.x), "f"(b1.y), "f"(b1.z), "f"(b1.w) : "memory");
}

// General edge step (steps 1..4), 2 edges/thread.
// TBL: 0 = node table g_Rn indexed by g_srv; 1 = g_RA by g_rv; 2 = g_RB by g_rv.
// OUT: 0 = none (last step); 1 = write g_RA; 2 = write g_RB.
template <int TBL, int OUT>
__global__ void __launch_bounds__(256) edge_step_kernel() {
    int t = blockIdx.x * 256 + threadIdx.x;
    int e0 = t * 2;

    int2 ss = *(const int2*)(g_src + e0);
    int2 dd = *(const int2*)(g_dst + e0);
    int2 ii = (TBL == 0) ? *(const int2*)(g_srv + e0) : *(const int2*)(g_rv + e0);

    const __half* __restrict__ tbl =
        (TBL == 0) ? g_Rn : (TBL == 1 ? g_RA : g_RB);

    // issue all gathers up-front (max MLP)
    float4 b00 = *(const float4*)(g_B + ss.x * NC);
    float4 b01 = *(const float4*)(g_B + ss.x * NC + 4);
    float4 b10 = *(const float4*)(g_B + ss.y * NC);
    float4 b11 = *(const float4*)(g_B + ss.y * NC + 4);
    uint4 rq0 = *(const uint4*)(tbl + (size_t)ii.x * NC);
    uint4 rq1 = *(const uint4*)(tbl + (size_t)ii.y * NC);

    const float beta = 19.085536923187668f;  // e^3 - 1
    const float C2 = 3.2990000f;             // log(e^3 + 7)

    float u0[NC], u1[NC];
    {
        const __half2* h = (const __half2*)&rq0;
        float2 f0 = __half22float2(h[0]), f1 = __half22float2(h[1]);
        float2 f2 = __half22float2(h[2]), f3 = __half22float2(h[3]);
        u0[0] = b00.x * f0.x; u0[1] = b00.y * f0.y;
        u0[2] = b00.z * f1.x; u0[3] = b00.w * f1.y;
        u0[4] = b01.x * f2.x; u0[5] = b01.y * f2.y;
        u0[6] = b01.z * f3.x; u0[7] = b01.w * f3.y;
    }
    {
        const __half2* h = (const __half2*)&rq1;
        float2 f0 = __half22float2(h[0]), f1 = __half22float2(h[1]);
        float2 f2 = __half22float2(h[2]), f3 = __half22float2(h[3]);
        u1[0] = b10.x * f0.x; u1[1] = b10.y * f0.y;
        u1[2] = b10.z * f1.x; u1[3] = b10.w * f1.y;
        u1[4] = b11.x * f2.x; u1[5] = b11.y * f2.y;
        u1[6] = b11.z * f3.x; u1[7] = b11.w * f3.y;
    }

    float U0 = ((u0[0] + u0[1]) + (u0[2] + u0[3])) + ((u0[4] + u0[5]) + (u0[6] + u0[7]));
    float U1 = ((u1[0] + u1[1]) + (u1[2] + u1[3])) + ((u1[4] + u1[5]) + (u1[6] + u1[7]));
    float bi0 = beta * frcp(U0);
    float bi1 = beta * frcp(U1);

    float lg0[NC], lg1[NC], Rn0[NC], Rn1[NC];
#pragma unroll
    for (int c = 0; c < NC; c++) {
        float q0 = fmaf(bi0, u0[c], 1.0f);
        float q1 = fmaf(bi1, u1[c], 1.0f);
        lg0[c] = __logf(q0) - C2;
        lg1[c] = __logf(q1) - C2;
        if (OUT != 0) { Rn0[c] = frcp(q0); Rn1[c] = frcp(q1); }
    }

    if (OUT != 0) {
        __half* __restrict__ Rnext = (OUT == 1) ? g_RA : g_RB;
        uint4 o0, o1;
        __half2* h0 = (__half2*)&o0;
        __half2* h1 = (__half2*)&o1;
        h0[0] = __floats2half2_rn(Rn0[0], Rn0[1]);
        h0[1] = __floats2half2_rn(Rn0[2], Rn0[3]);
        h0[2] = __floats2half2_rn(Rn0[4], Rn0[5]);
        h0[3] = __floats2half2_rn(Rn0[6], Rn0[7]);
        h1[0] = __floats2half2_rn(Rn1[0], Rn1[1]);
        h1[1] = __floats2half2_rn(Rn1[2], Rn1[3]);
        h1[2] = __floats2half2_rn(Rn1[4], Rn1[5]);
        h1[3] = __floats2half2_rn(Rn1[6], Rn1[7]);
        *(uint4*)(Rnext + (size_t)e0 * NC) = o0;
        *(uint4*)(Rnext + (size_t)(e0 + 1) * NC) = o1;
    }

    float* p0 = g_agg + dd.x * NC;
    float* p1 = g_agg + dd.y * NC;
    asm volatile("red.global.add.v4.f32 [%0], {%1,%2,%3,%4};"
                 :: "l"(p0), "f"(lg0[0]), "f"(lg0[1]), "f"(lg0[2]), "f"(lg0[3]) : "memory");
    asm volatile("red.global.add.v4.f32 [%0], {%1,%2,%3,%4};"
                 :: "l"(p0 + 4), "f"(lg0[4]), "f"(lg0[5]), "f"(lg0[6]), "f"(lg0[7]) : "memory");
    asm volatile("red.global.add.v4.f32 [%0], {%1,%2,%3,%4};"
                 :: "l"(p1), "f"(lg1[0]), "f"(lg1[1]), "f"(lg1[2]), "f"(lg1[3]) : "memory");
    asm volatile("red.global.add.v4.f32 [%0], {%1,%2,%3,%4};"
                 :: "l"(p1 + 4), "f"(lg1[4]), "f"(lg1[5]), "f"(lg1[6]), "f"(lg1[7]) : "memory");
}

// Node update: log_b = normalize(agg) (agg already includes log_b0).
// Non-last: store B = exp(log_b), reset agg = log_b0. Last: write log_b to out.
template <bool LAST>
__global__ void __launch_bounds__(256) node_kernel(float* __restrict__ out) {
    int n = blockIdx.x * 256 + threadIdx.x;
    if (n >= NN) return;

    float4 a0 = *(const float4*)(g_agg + n * NC);
    float4 a1 = *(const float4*)(g_agg + n * NC + 4);
    float v[NC] = {a0.x, a0.y, a0.z, a0.w, a1.x, a1.y, a1.z, a1.w};

    float m = v[0];
#pragma unroll
    for (int c = 1; c < NC; c++) m = fmaxf(m, v[c]);

    float e[NC], S = 0.f;
#pragma unroll
    for (int c = 0; c < NC; c++) {
        e[c] = __expf(v[c] - m);
        S += e[c];
    }

    if (LAST) {
        float lS = __logf(S);
        *(float4*)(out + n * NC) =
            make_float4(v[0] - m - lS, v[1] - m - lS, v[2] - m - lS, v[3] - m - lS);
        *(float4*)(out + n * NC + 4) =
            make_float4(v[4] - m - lS, v[5] - m - lS, v[6] - m - lS, v[7] - m - lS);
    } else {
        float iS = frcp(S);
        *(float4*)(g_B + n * NC) = make_float4(e[0] * iS, e[1] * iS, e[2] * iS, e[3] * iS);
        *(float4*)(g_B + n * NC + 4) = make_float4(e[4] * iS, e[5] * iS, e[6] * iS, e[7] * iS);
        float4 l0 = *(const float4*)(g_logb0 + n * NC);
        float4 l1 = *(const float4*)(g_logb0 + n * NC + 4);
        *(float4*)(g_agg + n * NC) = l0;
        *(float4*)(g_agg + n * NC + 4) = l1;
    }
}

extern "C" void kernel_launch(void* const* d_in, const int* in_sizes, int n_in,
                              void* d_out, int out_size) {
    const float* x = (const float*)d_in[0];
    const float* W = (const float*)d_in[1];
    const float* bias = (const float*)d_in[2];
    const void* ei = d_in[3];
    const void* rv = d_in[4];
    float* out = (float*)d_out;

    const int EB = (NE + 255) / 256;       // 6250
    const int EB2 = NE / 512;              // 3125 (2 edges/thread)
    const int NB = (NN + 255) / 256;       // 196
    const int TBK = (NN + TTB - 1) / TTB;  // 782

    reset_flag_kernel<<<1, 1>>>();
    detect_kernel<<<1, 256>>>((const int*)ei);
    prep_kernel<<<EB, 256>>>(ei, rv);
    prep2_kernel<<<EB, 256>>>();
    transform_kernel<<<TBK, TTB>>>(x, W, bias);

    // step 0: per-node messages, pure gather-scatter
    step0_kernel<<<EB2, 256>>>();
    node_kernel<false><<<NB, 256>>>(nullptr);
    // step 1: R from node table via srv, write RA
    edge_step_kernel<0, 1><<<EB2, 256>>>();
    node_kernel<false><<<NB, 256>>>(nullptr);
    // step 2: read RA, write RB
    edge_step_kernel<1, 2><<<EB2, 256>>>();
    node_kernel<false><<<NB, 256>>>(nullptr);
    // step 3: read RB, write RA
    edge_step_kernel<2, 1><<<EB2, 256>>>();
    node_kernel<false><<<NB, 256>>>(nullptr);
    // step 4: read RA, no write, final
    edge_step_kernel<1, 0><<<EB2, 256>>>();
    node_kernel<true><<<NB, 256>>>(out);
}

// round 6
// speedup vs baseline: 1.0640x; 1.0640x over previous
#include <cuda_runtime.h>
#include <cuda_fp16.h>
#include <cstdint>

#define NN 50000
#define DIN 256
#define NC 8
#define NE 1600000
#define TTB 64
#define TBK 782    // ceil(NN/TTB) transform blocks
#define PBK 6250   // NE/256 prep blocks

// ---- static device scratch (allocation-free contract) ----
__device__ __align__(16) float g_logb0[NN * NC];
__device__ __align__(16) float g_agg[NN * NC];
__device__ __align__(16) __half g_Bh[NN * NC];    // fp16 beliefs
__device__ __align__(16) __half g_m0h[NN * NC];   // fp16 step-0 per-node message
__device__ __align__(16) __half g_Rn[NN * NC];    // fp16 step-0 reciprocal msg
__device__ __align__(16) __half g_RA[NE * NC];    // fp16 reciprocal messages (ping)
__device__ __align__(16) __half g_RB[NE * NC];    // fp16 reciprocal messages (pong)
__device__ __align__(16) int4 g_idx[NE];          // (src, dst, srv, rv)
__device__ int g_odd_nonzero;  // !=0 -> indices are int32; ==0 -> int64

__device__ __forceinline__ float frcp(float x) {
    float r;
    asm("rcp.approx.f32 %0, %1;" : "=f"(r) : "f"(x));
    return r;
}

#define CP_ASYNC_16(saddr, gptr) \
    asm volatile("cp.async.cg.shared.global [%0], [%1], 16;" :: "r"(saddr), "l"(gptr))
#define CP_COMMIT() asm volatile("cp.async.commit_group;")
#define CP_WAIT(n) asm volatile("cp.async.wait_group %0;" :: "n"(n))

// --- dtype detection (single block; includes flag reset) ---
// Sample odd 32-bit words of the first 4096 index pairs.
// int64 layout: high halves of nonneg values < 2^31 -> all zero.
// int32 layout: uniform node ids -> P(all zero) ~ 0.
__global__ void __launch_bounds__(256) detect_kernel(const int* __restrict__ w) {
    if (threadIdx.x == 0) g_odd_nonzero = 0;
    __syncthreads();
    int v = 0;
#pragma unroll
    for (int j = 0; j < 16; j++) {
        int i = threadIdx.x + j * 256;
        v |= w[2 * i + 1];
    }
    unsigned any = __ballot_sync(0xffffffffu, v != 0);
    if ((threadIdx.x & 31) == 0 && any) atomicOr(&g_odd_nonzero, 1);
}

// ---- fused prep + transform ----
// Blocks [0, TBK): transform (log_softmax of x@W+b, plus step-0 message tables).
// Blocks [TBK, TBK+PBK): index compaction into packed int4, with
// srv[e] = src[rv[e]] read DIRECTLY from the input array (no dependency).
__global__ void __launch_bounds__(256) fused_prep_transform(
    const float* __restrict__ x, const float* __restrict__ W,
    const float* __restrict__ bias, const void* __restrict__ ei,
    const void* __restrict__ rv) {
    if (blockIdx.x >= TBK) {
        // ------- prep branch -------
        int e = (blockIdx.x - TBK) * 256 + threadIdx.x;
        if (e < NE) {
            int s, d, r, sv;
            if (g_odd_nonzero) {  // int32 inputs
                const int* e32 = (const int*)ei;
                const int* r32 = (const int*)rv;
                s = e32[e];
                d = e32[NE + e];
                r = r32[e];
                sv = e32[r];
            } else {  // int64 inputs
                const long long* e64 = (const long long*)ei;
                const long long* r64 = (const long long*)rv;
                s = (int)e64[e];
                d = (int)e64[NE + e];
                r = (int)r64[e];
                sv = (int)e64[r];
            }
            g_idx[e] = make_int4(s, d, sv, r);
        }
        return;
    }

    // ------- transform branch (64 nodes/block, 256 threads load, 64 compute) -------
    __shared__ __align__(16) float sx[2][TTB][36];
    __shared__ __align__(16) float sW[DIN * NC];
    __shared__ float sb[NC];

    int tid = threadIdx.x;
    for (int i = tid; i < DIN * NC; i += 256) sW[i] = W[i];
    if (tid < NC) sb[tid] = bias[tid];

    int node0 = blockIdx.x * TTB;
    int n = node0 + tid;  // only valid for tid < TTB

    unsigned int sx_base = (unsigned int)__cvta_generic_to_shared(&sx[0][0][0]);

    // issue chunk 0 into buffer 0 (all 256 threads, 2 float4 each)
#pragma unroll
    for (int i = 0; i < 2; i++) {
        int lin = i * 256 + tid;          // 0..511
        int row = lin >> 3, c4 = lin & 7;
        int nr = node0 + row;
        if (nr < NN) {
            unsigned int sa = sx_base + (unsigned int)((row * 36 + c4 * 4) * 4);
            CP_ASYNC_16(sa, x + (size_t)nr * DIN + c4 * 4);
        }
    }
    CP_COMMIT();

    float acc[NC] = {0.f, 0.f, 0.f, 0.f, 0.f, 0.f, 0.f, 0.f};
    int buf = 0;

#pragma unroll 1
    for (int chunk = 0; chunk < DIN / 32; chunk++) {
        if (chunk + 1 < DIN / 32) {
            int ob = buf ^ 1;
#pragma unroll
            for (int i = 0; i < 2; i++) {
                int lin = i * 256 + tid;
                int row = lin >> 3, c4 = lin & 7;
                int nr = node0 + row;
                if (nr < NN) {
                    unsigned int sa = sx_base +
                                      (unsigned int)(((ob * TTB + row) * 36 + c4 * 4) * 4);
                    CP_ASYNC_16(sa, x + (size_t)nr * DIN + (chunk + 1) * 32 + c4 * 4);
                }
            }
            CP_COMMIT();
            CP_WAIT(1);
        } else {
            CP_WAIT(0);
        }
        __syncthreads();

        if (tid < TTB) {
#pragma unroll
            for (int k4 = 0; k4 < 8; k4++) {
                float4 xv = *(const float4*)&sx[buf][tid][k4 * 4];
                int kg = chunk * 32 + k4 * 4;
                float xs[4] = {xv.x, xv.y, xv.z, xv.w};
#pragma unroll
                for (int j = 0; j < 4; j++) {
                    float4 w0 = *(const float4*)&sW[(kg + j) * NC];
                    float4 w1 = *(const float4*)&sW[(kg + j) * NC + 4];
                    acc[0] = fmaf(xs[j], w0.x, acc[0]);
                    acc[1] = fmaf(xs[j], w0.y, acc[1]);
                    acc[2] = fmaf(xs[j], w0.z, acc[2]);
                    acc[3] = fmaf(xs[j], w0.w, acc[3]);
                    acc[4] = fmaf(xs[j], w1.x, acc[4]);
                    acc[5] = fmaf(xs[j], w1.y, acc[5]);
                    acc[6] = fmaf(xs[j], w1.z, acc[6]);
                    acc[7] = fmaf(xs[j], w1.w, acc[7]);
                }
            }
        }
        __syncthreads();
        buf ^= 1;
    }

    if (tid >= TTB || n >= NN) return;

    float m = -3.4e38f;
#pragma unroll
    for (int c = 0; c < NC; c++) {
        acc[c] += sb[c];
        m = fmaxf(m, acc[c]);
    }
    float e[NC], S = 0.f;
#pragma unroll
    for (int c = 0; c < NC; c++) {
        e[c] = __expf(acc[c] - m);
        S += e[c];
    }
    float lS = __logf(S);
    float iS = frcp(S);

    const float beta = 19.085536923187668f;  // e^3 - 1
    const float C2 = 3.2990000f;             // log(e^3 + 7)

    float lb[NC], B[NC], m0[NC], Rn[NC];
#pragma unroll
    for (int c = 0; c < NC; c++) {
        lb[c] = acc[c] - m - lS;
        B[c] = e[c] * iS;
        float qp = fmaf(beta, B[c], 1.0f);
        m0[c] = __logf(qp) - C2;
        Rn[c] = frcp(qp);
    }

    *(float4*)(g_logb0 + n * NC) = make_float4(lb[0], lb[1], lb[2], lb[3]);
    *(float4*)(g_logb0 + n * NC + 4) = make_float4(lb[4], lb[5], lb[6], lb[7]);
    *(float4*)(g_agg + n * NC) = make_float4(lb[0], lb[1], lb[2], lb[3]);
    *(float4*)(g_agg + n * NC + 4) = make_float4(lb[4], lb[5], lb[6], lb[7]);

    uint4 bq, mq, rq;
    __half2* bh = (__half2*)&bq;
    __half2* mh = (__half2*)&mq;
    __half2* rh = (__half2*)&rq;
#pragma unroll
    for (int c = 0; c < 4; c++) {
        bh[c] = __floats2half2_rn(B[2 * c], B[2 * c + 1]);
        mh[c] = __floats2half2_rn(m0[2 * c], m0[2 * c + 1]);
        rh[c] = __floats2half2_rn(Rn[2 * c], Rn[2 * c + 1]);
    }
    *(uint4*)(g_Bh + n * NC) = bq;
    *(uint4*)(g_m0h + n * NC) = mq;
    *(uint4*)(g_Rn + n * NC) = rq;
}

__device__ __forceinline__ void h8_to_f8(uint4 q, float* f) {
    const __half2* h = (const __half2*)&q;
#pragma unroll
    for (int c = 0; c < 4; c++) {
        float2 t = __half22float2(h[c]);
        f[2 * c] = t.x;
        f[2 * c + 1] = t.y;
    }
}

// step 0: agg[dst] += m0[src]  (pure gather-scatter, 2 edges/thread)
__global__ void __launch_bounds__(256) step0_kernel() {
    int t = blockIdx.x * 256 + threadIdx.x;
    int e0 = t * 2;
    int4 i0 = g_idx[e0];
    int4 i1 = g_idx[e0 + 1];

    uint4 q0 = *(const uint4*)(g_m0h + i0.x * NC);
    uint4 q1 = *(const uint4*)(g_m0h + i1.x * NC);
    float a[NC], b[NC];
    h8_to_f8(q0, a);
    h8_to_f8(q1, b);

    float* p0 = g_agg + i0.y * NC;
    float* p1 = g_agg + i1.y * NC;
    asm volatile("red.global.add.v4.f32 [%0], {%1,%2,%3,%4};"
                 :: "l"(p0), "f"(a[0]), "f"(a[1]), "f"(a[2]), "f"(a[3]) : "memory");
    asm volatile("red.global.add.v4.f32 [%0], {%1,%2,%3,%4};"
                 :: "l"(p0 + 4), "f"(a[4]), "f"(a[5]), "f"(a[6]), "f"(a[7]) : "memory");
    asm volatile("red.global.add.v4.f32 [%0], {%1,%2,%3,%4};"
                 :: "l"(p1), "f"(b[0]), "f"(b[1]), "f"(b[2]), "f"(b[3]) : "memory");
    asm volatile("red.global.add.v4.f32 [%0], {%1,%2,%3,%4};"
                 :: "l"(p1 + 4), "f"(b[4]), "f"(b[5]), "f"(b[6]), "f"(b[7]) : "memory");
}

// General edge step (steps 1..4), 2 edges/thread.
// TBL: 0 = node table g_Rn indexed by srv; 1 = g_RA by rv; 2 = g_RB by rv.
// OUT: 0 = none (last step); 1 = write g_RA; 2 = write g_RB.
template <int TBL, int OUT>
__global__ void __launch_bounds__(256) edge_step_kernel() {
    int t = blockIdx.x * 256 + threadIdx.x;
    int e0 = t * 2;

    int4 i0 = g_idx[e0];
    int4 i1 = g_idx[e0 + 1];
    int r0i = (TBL == 0) ? i0.z : i0.w;
    int r1i = (TBL == 0) ? i1.z : i1.w;

    const __half* __restrict__ tbl =
        (TBL == 0) ? g_Rn : (TBL == 1 ? g_RA : g_RB);

    // issue all gathers up-front (max MLP)
    uint4 bq0 = *(const uint4*)(g_Bh + i0.x * NC);
    uint4 bq1 = *(const uint4*)(g_Bh + i1.x * NC);
    uint4 rq0 = *(const uint4*)(tbl + (size_t)r0i * NC);
    uint4 rq1 = *(const uint4*)(tbl + (size_t)r1i * NC);

    const float beta = 19.085536923187668f;  // e^3 - 1
    const float C2 = 3.2990000f;             // log(e^3 + 7)

    float bf0[NC], bf1[NC], rf0[NC], rf1[NC];
    h8_to_f8(bq0, bf0);
    h8_to_f8(bq1, bf1);
    h8_to_f8(rq0, rf0);
    h8_to_f8(rq1, rf1);

    float u0[NC], u1[NC];
#pragma unroll
    for (int c = 0; c < NC; c++) {
        u0[c] = bf0[c] * rf0[c];
        u1[c] = bf1[c] * rf1[c];
    }

    float U0 = ((u0[0] + u0[1]) + (u0[2] + u0[3])) + ((u0[4] + u0[5]) + (u0[6] + u0[7]));
    float U1 = ((u1[0] + u1[1]) + (u1[2] + u1[3])) + ((u1[4] + u1[5]) + (u1[6] + u1[7]));
    float bi0 = beta * frcp(U0);
    float bi1 = beta * frcp(U1);

    float lg0[NC], lg1[NC], Rn0[NC], Rn1[NC];
#pragma unroll
    for (int c = 0; c < NC; c++) {
        float q0 = fmaf(bi0, u0[c], 1.0f);
        float q1 = fmaf(bi1, u1[c], 1.0f);
        lg0[c] = __logf(q0) - C2;
        lg1[c] = __logf(q1) - C2;
        if (OUT != 0) { Rn0[c] = frcp(q0); Rn1[c] = frcp(q1); }
    }

    if (OUT != 0) {
        __half* __restrict__ Rnext = (OUT == 1) ? g_RA : g_RB;
        uint4 o0, o1;
        __half2* h0 = (__half2*)&o0;
        __half2* h1 = (__half2*)&o1;
#pragma unroll
        for (int c = 0; c < 4; c++) {
            h0[c] = __floats2half2_rn(Rn0[2 * c], Rn0[2 * c + 1]);
            h1[c] = __floats2half2_rn(Rn1[2 * c], Rn1[2 * c + 1]);
        }
        *(uint4*)(Rnext + (size_t)e0 * NC) = o0;
        *(uint4*)(Rnext + (size_t)(e0 + 1) * NC) = o1;
    }

    float* p0 = g_agg + i0.y * NC;
    float* p1 = g_agg + i1.y * NC;
    asm volatile("red.global.add.v4.f32 [%0], {%1,%2,%3,%4};"
                 :: "l"(p0), "f"(lg0[0]), "f"(lg0[1]), "f"(lg0[2]), "f"(lg0[3]) : "memory");
    asm volatile("red.global.add.v4.f32 [%0], {%1,%2,%3,%4};"
                 :: "l"(p0 + 4), "f"(lg0[4]), "f"(lg0[5]), "f"(lg0[6]), "f"(lg0[7]) : "memory");
    asm volatile("red.global.add.v4.f32 [%0], {%1,%2,%3,%4};"
                 :: "l"(p1), "f"(lg1[0]), "f"(lg1[1]), "f"(lg1[2]), "f"(lg1[3]) : "memory");
    asm volatile("red.global.add.v4.f32 [%0], {%1,%2,%3,%4};"
                 :: "l"(p1 + 4), "f"(lg1[4]), "f"(lg1[5]), "f"(lg1[6]), "f"(lg1[7]) : "memory");
}

// Node update: log_b = normalize(agg) (agg already includes log_b0).
// Non-last: store Bh = exp(log_b) fp16, reset agg = log_b0. Last: write to out.
template <bool LAST>
__global__ void __launch_bounds__(256) node_kernel(float* __restrict__ out) {
    int n = blockIdx.x * 256 + threadIdx.x;
    if (n >= NN) return;

    float4 a0 = *(const float4*)(g_agg + n * NC);
    float4 a1 = *(const float4*)(g_agg + n * NC + 4);
    float v[NC] = {a0.x, a0.y, a0.z, a0.w, a1.x, a1.y, a1.z, a1.w};

    float m = v[0];
#pragma unroll
    for (int c = 1; c < NC; c++) m = fmaxf(m, v[c]);

    float e[NC], S = 0.f;
#pragma unroll
    for (int c = 0; c < NC; c++) {
        e[c] = __expf(v[c] - m);
        S += e[c];
    }

    if (LAST) {
        float lS = __logf(S);
        *(float4*)(out + n * NC) =
            make_float4(v[0] - m - lS, v[1] - m - lS, v[2] - m - lS, v[3] - m - lS);
        *(float4*)(out + n * NC + 4) =
            make_float4(v[4] - m - lS, v[5] - m - lS, v[6] - m - lS, v[7] - m - lS);
    } else {
        float iS = frcp(S);
        uint4 bq;
        __half2* bh = (__half2*)&bq;
#pragma unroll
        for (int c = 0; c < 4; c++)
            bh[c] = __floats2half2_rn(e[2 * c] * iS, e[2 * c + 1] * iS);
        *(uint4*)(g_Bh + n * NC) = bq;
        float4 l0 = *(const float4*)(g_logb0 + n * NC);
        float4 l1 = *(const float4*)(g_logb0 + n * NC + 4);
        *(float4*)(g_agg + n * NC) = l0;
        *(float4*)(g_agg + n * NC + 4) = l1;
    }
}

extern "C" void kernel_launch(void* const* d_in, const int* in_sizes, int n_in,
                              void* d_out, int out_size) {
    const float* x = (const float*)d_in[0];
    const float* W = (const float*)d_in[1];
    const float* bias = (const float*)d_in[2];
    const void* ei = d_in[3];
    const void* rv = d_in[4];
    float* out = (float*)d_out;

    const int EB2 = NE / 512;  // 3125 (2 edges/thread)
    const int NB = (NN + 255) / 256;

    detect_kernel<<<1, 256>>>((const int*)ei);
    fused_prep_transform<<<TBK + PBK, 256>>>(x, W, bias, ei, rv);

    // step 0: per-node messages, pure gather-scatter
    step0_kernel<<<EB2, 256>>>();
    node_kernel<false><<<NB, 256>>>(nullptr);
    // step 1: R from node table via srv, write RA
    edge_step_kernel<0, 1><<<EB2, 256>>>();
    node_kernel<false><<<NB, 256>>>(nullptr);
    // step 2: read RA, write RB
    edge_step_kernel<1, 2><<<EB2, 256>>>();
    node_kernel<false><<<NB, 256>>>(nullptr);
    // step 3: read RB, write RA
    edge_step_kernel<2, 1><<<EB2, 256>>>();
    node_kernel<false><<<NB, 256>>>(nullptr);
    // step 4: read RA, no write, final
    edge_step_kernel<1, 0><<<EB2, 256>>>();
    node_kernel<true><<<NB, 256>>>(out);
}